// round 16
// baseline (speedup 1.0000x reference)
#include <cuda_runtime.h>
#include <cuda_bf16.h>
#include <math.h>
#include <float.h>
#include <stdint.h>

#define NROWS 8192
#define FDIM 256
#define NCLS 64
#define KNNK 5
#define MAXSTEPS 100
#define LOOPBLK 256
#define CANDMAX 256

// ---------------- device scratch ----------------
__device__ float          g_fn[NROWS * FDIM];
__device__ __nv_bfloat16  g_fnb[NROWS * FDIM];
__device__ float          g_sq[NROWS];
__device__ __nv_bfloat16  g_dotsb[(size_t)NROWS * NROWS];   // bf16 DISTANCES
__device__ float          g_unary[NROWS * NCLS];
__device__ float          g_Ya[NROWS * NCLS];
__device__ float          g_Yb[NROWS * NCLS];
__device__ int            g_idx[NROWS * KNNK];
__device__ float          g_EpartF[2][LOOPBLK];
__device__ unsigned       g_barA;
__device__ volatile unsigned g_barE;

// ---------------- helpers ----------------
__device__ __forceinline__ uint32_t smem_u32(const void* p) {
    uint32_t a;
    asm("{ .reg .u64 t; cvta.to.shared.u64 t, %1; cvt.u32.u64 %0, t; }" : "=r"(a) : "l"(p));
    return a;
}
__device__ __forceinline__ uint32_t packbf(float lo, float hi) {
    uint32_t r;
    asm("cvt.rn.bf16x2.f32 %0, %1, %2;" : "=r"(r) : "f"(hi), "f"(lo)); // d.lo = %2
    return r;
}
__device__ __forceinline__ void cp_async16(uint32_t saddr, const void* gaddr) {
    asm volatile("cp.async.cg.shared.global [%0], [%1], 16;" :: "r"(saddr), "l"(gaddr));
}
__device__ __forceinline__ void cp_commit() { asm volatile("cp.async.commit_group;"); }
__device__ __forceinline__ void cp_wait0() { asm volatile("cp.async.wait_group 0;"); }

// ---------------- normalize feats (fp32 + bf16), compute sq ----------------
__global__ void normalize_kernel(const float* __restrict__ feats) {
    int row = blockIdx.x;
    int t = threadIdx.x;
    __shared__ float red[8];
    float x = feats[row * FDIM + t];
    float v = x * x;
    #pragma unroll
    for (int o = 16; o; o >>= 1) v += __shfl_xor_sync(0xffffffffu, v, o);
    if ((t & 31) == 0) red[t >> 5] = v;
    __syncthreads();
    float tot = red[0] + red[1] + red[2] + red[3] + red[4] + red[5] + red[6] + red[7];
    float y = x / fmaxf(sqrtf(tot), 1e-12f);
    g_fn[row * FDIM + t] = y;
    g_fnb[row * FDIM + t] = __float2bfloat16(y);
    float v2 = y * y;
    #pragma unroll
    for (int o = 16; o; o >>= 1) v2 += __shfl_xor_sync(0xffffffffu, v2, o);
    __syncthreads();
    if ((t & 31) == 0) red[t >> 5] = v2;
    __syncthreads();
    if (t == 0)
        g_sq[row] = red[0] + red[1] + red[2] + red[3] + red[4] + red[5] + red[6] + red[7];
}

// ---------------- unary + Y0 (also resets loop barrier state) ----------------
__global__ void unary_y0_kernel(const float* __restrict__ scores) {
    if (blockIdx.x == 0 && threadIdx.x == 0) { g_barA = 0; g_barE = 0; }
    int w = blockIdx.x * (blockDim.x >> 5) + (threadIdx.x >> 5);
    int lane = threadIdx.x & 31;
    if (w >= NROWS) return;
    float2 s = *(const float2*)(scores + w * NCLS + lane * 2);
    float u0 = -logf(s.x + 1e-10f);
    float u1 = -logf(s.y + 1e-10f);
    *(float2*)(g_unary + w * NCLS + lane * 2) = make_float2(u0, u1);
    float z0 = -u0, z1 = -u1;
    float m = fmaxf(z0, z1);
    #pragma unroll
    for (int o = 16; o; o >>= 1) m = fmaxf(m, __shfl_xor_sync(0xffffffffu, m, o));
    float e0 = expf(z0 - m), e1 = expf(z1 - m);
    float sm = e0 + e1;
    #pragma unroll
    for (int o = 16; o; o >>= 1) sm += __shfl_xor_sync(0xffffffffu, sm, o);
    float inv = 1.f / sm;
    *(float2*)(g_Ya + w * NCLS + lane * 2) = make_float2(e0 * inv, e1 * inv);
}

// ---------------- bf16 mma.sync symmetric GEMM -> bf16 DISTANCE matrix ----------------
#define BM 128
#define BN 128
#define BKC 64
#define AST 72     // padded smem row stride (bf16): 144 B = 9 x 16B chunks (odd shift)
#define TST 136    // transpose-staging stride (bf16): 272 B
#define NBLK (NROWS / BM) // 64

__global__ void __launch_bounds__(256) gemm_mma_kernel() {
    __shared__ __align__(16) unsigned char pool[73728];
    __nv_bfloat16 (*As)[BM][AST] = (__nv_bfloat16 (*)[BM][AST])pool;
    __nv_bfloat16 (*Bs)[BN][AST] = (__nv_bfloat16 (*)[BN][AST])(pool + 36864);
    __nv_bfloat16 (*Ts)[TST] = (__nv_bfloat16 (*)[TST])pool;  // reused for mirror

    // triangular block decode
    int tt = blockIdx.x, bi = 0;
    while (tt >= NBLK - bi) { tt -= NBLK - bi; bi++; }
    int bj = bi + tt;
    int iBase = bi * BM, jBase = bj * BN;

    int tid = threadIdx.x, lane = tid & 31, wid = tid >> 5;
    int wm = wid & 1, wn = wid >> 1;   // warp tile 64x32 at (wm*64, wn*32)

    // loaders: 64 cols = 8 x 16B chunks per row; 32 rows per pass, 4 passes
    int lrow = tid >> 3;               // 0..31
    int lch = (tid & 7) * 8;           // bf16 offset of 16B chunk
    const __nv_bfloat16* gA = g_fnb + (size_t)(iBase + lrow) * FDIM + lch;
    const __nv_bfloat16* gB = g_fnb + (size_t)(jBase + lrow) * FDIM + lch;

    float acc[4][4][4];
    #pragma unroll
    for (int mi = 0; mi < 4; ++mi)
        #pragma unroll
        for (int ni = 0; ni < 4; ++ni)
            #pragma unroll
            for (int q = 0; q < 4; ++q) acc[mi][ni][q] = 0.f;

    int aRow = wm * 64 + (lane & 15);
    int aCol = ((lane >> 4) << 3);
    int bRow = wn * 32 + (lane & 7);
    int bCol = ((lane >> 3) & 1) << 3;

    // prefetch stage 0 (cols 0..63)
    #pragma unroll
    for (int p = 0; p < 4; ++p) {
        cp_async16(smem_u32(&As[0][lrow + p * 32][lch]), gA + p * 32 * FDIM);
        cp_async16(smem_u32(&Bs[0][lrow + p * 32][lch]), gB + p * 32 * FDIM);
    }
    cp_commit();

    #pragma unroll 1
    for (int kk = 0; kk < FDIM / BKC; ++kk) {
        int buf = kk & 1;
        cp_wait0();
        __syncthreads();                      // single barrier per stage
        if (kk < FDIM / BKC - 1) {
            int nb = buf ^ 1, k0 = (kk + 1) * BKC;
            #pragma unroll
            for (int p = 0; p < 4; ++p) {
                cp_async16(smem_u32(&As[nb][lrow + p * 32][lch]), gA + p * 32 * FDIM + k0);
                cp_async16(smem_u32(&Bs[nb][lrow + p * 32][lch]), gB + p * 32 * FDIM + k0);
            }
            cp_commit();
        }
        #pragma unroll
        for (int ks = 0; ks < 4; ++ks) {      // 4 x k16 per stage
            int k0 = ks * 16;
            uint32_t a[4][4], b[4][2];
            #pragma unroll
            for (int mi = 0; mi < 4; ++mi) {
                uint32_t ad = smem_u32(&As[buf][aRow + mi * 16][k0 + aCol]);
                asm volatile(
                    "ldmatrix.sync.aligned.m8n8.x4.shared.b16 {%0,%1,%2,%3}, [%4];"
                    : "=r"(a[mi][0]), "=r"(a[mi][1]), "=r"(a[mi][2]), "=r"(a[mi][3])
                    : "r"(ad));
            }
            #pragma unroll
            for (int ni = 0; ni < 4; ++ni) {
                uint32_t bd = smem_u32(&Bs[buf][bRow + ni * 8][k0 + bCol]);
                asm volatile(
                    "ldmatrix.sync.aligned.m8n8.x2.shared.b16 {%0,%1}, [%2];"
                    : "=r"(b[ni][0]), "=r"(b[ni][1])
                    : "r"(bd));
            }
            #pragma unroll
            for (int mi = 0; mi < 4; ++mi)
                #pragma unroll
                for (int ni = 0; ni < 4; ++ni)
                    asm volatile(
                        "mma.sync.aligned.m16n8k16.row.col.f32.bf16.bf16.f32 "
                        "{%0,%1,%2,%3}, {%4,%5,%6,%7}, {%8,%9}, {%0,%1,%2,%3};"
                        : "+f"(acc[mi][ni][0]), "+f"(acc[mi][ni][1]),
                          "+f"(acc[mi][ni][2]), "+f"(acc[mi][ni][3])
                        : "r"(a[mi][0]), "r"(a[mi][1]), "r"(a[mi][2]), "r"(a[mi][3]),
                          "r"(b[ni][0]), "r"(b[ni][1]));
        }
        // no tail sync: next stage's wait+sync protects buffer reuse
    }

    // convert accumulators to distances: d = max(sqi + sqj - 2*dot, 0)
    int r0 = wm * 64 + (lane >> 2);
    int c0 = wn * 32 + (lane & 3) * 2;
    float sqr[8], sqc[8];
    #pragma unroll
    for (int mi = 0; mi < 4; ++mi) {
        sqr[2 * mi]     = __ldg(&g_sq[iBase + r0 + mi * 16]);
        sqr[2 * mi + 1] = __ldg(&g_sq[iBase + r0 + mi * 16 + 8]);
    }
    #pragma unroll
    for (int ni = 0; ni < 4; ++ni) {
        sqc[2 * ni]     = __ldg(&g_sq[jBase + c0 + ni * 8]);
        sqc[2 * ni + 1] = __ldg(&g_sq[jBase + c0 + ni * 8 + 1]);
    }
    float dd[4][4][4];
    #pragma unroll
    for (int mi = 0; mi < 4; ++mi)
        #pragma unroll
        for (int ni = 0; ni < 4; ++ni) {
            dd[mi][ni][0] = fmaxf(fmaf(-2.f, acc[mi][ni][0], sqr[2 * mi] + sqc[2 * ni]), 0.f);
            dd[mi][ni][1] = fmaxf(fmaf(-2.f, acc[mi][ni][1], sqr[2 * mi] + sqc[2 * ni + 1]), 0.f);
            dd[mi][ni][2] = fmaxf(fmaf(-2.f, acc[mi][ni][2], sqr[2 * mi + 1] + sqc[2 * ni]), 0.f);
            dd[mi][ni][3] = fmaxf(fmaf(-2.f, acc[mi][ni][3], sqr[2 * mi + 1] + sqc[2 * ni + 1]), 0.f);
        }

    // main tile write
    #pragma unroll
    for (int mi = 0; mi < 4; ++mi)
        #pragma unroll
        for (int ni = 0; ni < 4; ++ni) {
            size_t row = (size_t)(iBase + r0 + mi * 16);
            int col = jBase + c0 + ni * 8;
            *(uint32_t*)(g_dotsb + row * NROWS + col) =
                packbf(dd[mi][ni][0], dd[mi][ni][1]);
            *(uint32_t*)(g_dotsb + (row + 8) * NROWS + col) =
                packbf(dd[mi][ni][2], dd[mi][ni][3]);
        }

    // mirror (distance matrix is symmetric): smem-staged transpose
    if (bi != bj) {
        __syncthreads();   // all warps done reading As/Bs before pool reuse
        #pragma unroll
        for (int mi = 0; mi < 4; ++mi)
            #pragma unroll
            for (int ni = 0; ni < 4; ++ni) {
                int rr = r0 + mi * 16;
                int cc = c0 + ni * 8;
                Ts[cc][rr]         = __float2bfloat16(dd[mi][ni][0]);
                Ts[cc + 1][rr]     = __float2bfloat16(dd[mi][ni][1]);
                Ts[cc][rr + 8]     = __float2bfloat16(dd[mi][ni][2]);
                Ts[cc + 1][rr + 8] = __float2bfloat16(dd[mi][ni][3]);
            }
        __syncthreads();
        #pragma unroll
        for (int q = 0; q < 8; ++q) {
            int idx = q * 256 + tid;       // 2048 uint4 chunks: 16 per 128-col row
            int c = idx >> 4;              // 0..127
            int ch = (idx & 15) * 8;       // 0..120
            uint4 v = *(const uint4*)&Ts[c][ch];
            *(uint4*)(g_dotsb + (size_t)(jBase + c) * NROWS + iBase + ch) = v;
        }
    }
}

// ---------------- knn: threshold-select candidates + exact refine ----------------
__device__ __forceinline__ bool cless(float v1, int i1, float v2, int i2) {
    return (v1 < v2) || (v1 == v2 && i1 < i2);
}

__global__ void __launch_bounds__(256) knn_kernel() {
    __shared__ uint32_t sMin[256];
    __shared__ uint32_t sTau;
    __shared__ int sCnt;
    __shared__ int sCand[CANDMAX];
    __shared__ float sDv[CANDMAX];
    __shared__ int sDj[CANDMAX];

    int row = blockIdx.x;
    int t = threadIdx.x, lane = t & 31, wid = t >> 5;
    const uint4* __restrict__ dr = (const uint4*)(g_dotsb + (size_t)row * NROWS);

    // Pass A: per-thread min over 32 bf16 distances (4 uint4, kept in regs)
    uint4 vv[4];
    __nv_bfloat162 mn;
    #pragma unroll
    for (int i = 0; i < 4; ++i) {
        uint4 v = dr[i * 256 + t];
        vv[i] = v;
        __nv_bfloat162 a = *reinterpret_cast<__nv_bfloat162*>(&v.x);
        __nv_bfloat162 b = *reinterpret_cast<__nv_bfloat162*>(&v.y);
        __nv_bfloat162 c = *reinterpret_cast<__nv_bfloat162*>(&v.z);
        __nv_bfloat162 d = *reinterpret_cast<__nv_bfloat162*>(&v.w);
        __nv_bfloat162 m = __hmin2(__hmin2(a, b), __hmin2(c, d));
        mn = (i == 0) ? m : __hmin2(mn, m);
    }
    uint32_t myMin = (uint32_t)__bfloat16_as_ushort(__hmin(mn.x, mn.y));
    sMin[t] = myMin;
    __syncthreads();

    // warp 0: tau = 16th smallest of the 256 per-thread minima
    // (>=16 threads each own >=1 element <= tau -> d(16) <= tau >= d(6))
    if (t < 32) {
        uint32_t v[8];
        #pragma unroll
        for (int k = 0; k < 8; ++k)
            v[k] = (sMin[t + 32 * k] << 16) | (t + 32 * k);
        uint32_t tau = 0;
        #pragma unroll
        for (int r = 0; r < 16; ++r) {
            uint32_t g = v[0];
            #pragma unroll
            for (int k = 1; k < 8; ++k) g = min(g, v[k]);
            #pragma unroll
            for (int o = 16; o; o >>= 1) g = min(g, __shfl_xor_sync(0xffffffffu, g, o));
            tau = g >> 16;
            #pragma unroll
            for (int k = 0; k < 8; ++k)
                if (v[k] == g) v[k] = 0xFFFFFFFFu;
        }
        if (t == 0) { sTau = tau; sCnt = 0; }
    }
    __syncthreads();
    uint32_t tau = sTau;

    // Pass B: only threads whose min passed the filter rescan their 32 elements
    if (myMin <= tau) {
        #pragma unroll
        for (int i = 0; i < 4; ++i) {
            int j0 = (i * 256 + t) * 8;
            uint32_t w[4] = {vv[i].x, vv[i].y, vv[i].z, vv[i].w};
            #pragma unroll
            for (int k = 0; k < 4; ++k) {
                if ((w[k] & 0xFFFFu) <= tau) {
                    int p = atomicAdd(&sCnt, 1);
                    if (p < CANDMAX) sCand[p] = j0 + k * 2;
                }
                if ((w[k] >> 16) <= tau) {
                    int p = atomicAdd(&sCnt, 1);
                    if (p < CANDMAX) sCand[p] = j0 + k * 2 + 1;
                }
            }
        }
    }
    __syncthreads();
    int C = min(sCnt, CANDMAX);

    // exact fp32 refine for all candidates (warp per candidate, round robin)
    float sqi = g_sq[row];
    const float* fr = g_fn + (size_t)row * FDIM;
    float4 m0 = *(const float4*)(fr + lane * 8);
    float4 m1 = *(const float4*)(fr + lane * 8 + 4);
    for (int c = wid; c < C; c += 8) {
        int j = sCand[c];
        const float* fj = g_fn + (size_t)j * FDIM;
        float4 a0 = *(const float4*)(fj + lane * 8);
        float4 a1 = *(const float4*)(fj + lane * 8 + 4);
        float acc = m0.x * a0.x + m0.y * a0.y + m0.z * a0.z + m0.w * a0.w
                  + m1.x * a1.x + m1.y * a1.y + m1.z * a1.z + m1.w * a1.w;
        #pragma unroll
        for (int o = 16; o; o >>= 1) acc += __shfl_xor_sync(0xffffffffu, acc, o);
        if (lane == 0) {
            sDv[c] = fmaxf(sqi + g_sq[j] - 2.f * acc, 0.f);
            sDj[c] = j;
        }
    }
    __syncthreads();

    // exact top-5 (value then index tie-break), excluding self
    if (t == 0) {
        for (int r = 0; r < KNNK; ++r) {
            float best = FLT_MAX; int bi2 = 0x7fffffff, bc = -1;
            for (int c = 0; c < C; ++c)
                if (sDj[c] != row && cless(sDv[c], sDj[c], best, bi2)) {
                    best = sDv[c]; bi2 = sDj[c]; bc = c;
                }
            g_idx[row * KNNK + r] = bi2;
            sDv[bc] = FLT_MAX; sDj[bc] = 0x7fffffff;
        }
    }
}

// ---------------- persistent fused mean-field loop (measured-good R9 shape) ----------------
__device__ __forceinline__ void grid_sync_(unsigned epoch) {
    __syncthreads();
    if (threadIdx.x == 0) {
        __threadfence();
        unsigned prev = atomicAdd(&g_barA, 1u);
        if (prev == epoch * LOOPBLK - 1) {
            __threadfence();
            g_barE = epoch;
        } else {
            while (g_barE < epoch) { __nanosleep(32); }
            __threadfence();
        }
    }
    __syncthreads();
}

#define RPB (NROWS / LOOPBLK)   // 32 rows per block

__global__ void __launch_bounds__(256) loop_kernel(float* __restrict__ out) {
    __shared__ float sU[RPB * NCLS];
    __shared__ int sNb[RPB * KNNK];
    __shared__ float sWE[8];
    __shared__ float sEsh;
    __shared__ int sCv;
    int b = blockIdx.x, tid = threadIdx.x, wip = tid >> 5, lane = tid & 31;
    int row0 = b * RPB;

    for (int i = tid; i < RPB * NCLS / 4; i += 256)
        ((float4*)sU)[i] = ((const float4*)(g_unary + (size_t)row0 * NCLS))[i];
    for (int i = tid; i < RPB * KNNK; i += 256)
        sNb[i] = g_idx[row0 * KNNK + i];
    __syncthreads();

    float Eprev = __int_as_float(0x7F800000); // +inf
    int finalIt = MAXSTEPS - 1;

    for (int it = 0; it < MAXSTEPS; ++it) {
        const float* Yold = (it & 1) ? g_Yb : g_Ya;
        float* Ynew = (it & 1) ? g_Ya : g_Yb;
        float eAcc = 0.f;
        #pragma unroll
        for (int q = 0; q < RPB / 8; ++q) {
            int rl = wip * (RPB / 8) + q, row = row0 + rl;
            const int* nb = &sNb[rl * KNNK];
            float2 u = *(const float2*)&sU[rl * NCLS + lane * 2];
            float2 p0 = __ldcg((const float2*)(Yold + (size_t)nb[0] * NCLS + lane * 2));
            float2 p1 = __ldcg((const float2*)(Yold + (size_t)nb[1] * NCLS + lane * 2));
            float2 p2 = __ldcg((const float2*)(Yold + (size_t)nb[2] * NCLS + lane * 2));
            float2 p3 = __ldcg((const float2*)(Yold + (size_t)nb[3] * NCLS + lane * 2));
            float2 p4 = __ldcg((const float2*)(Yold + (size_t)nb[4] * NCLS + lane * 2));
            float z0 = -u.x + p0.x + p1.x + p2.x + p3.x + p4.x;
            float z1 = -u.y + p0.y + p1.y + p2.y + p3.y + p4.y;
            float m = fmaxf(z0, z1);
            #pragma unroll
            for (int o = 16; o; o >>= 1) m = fmaxf(m, __shfl_xor_sync(0xffffffffu, m, o));
            float e0 = __expf(z0 - m), e1 = __expf(z1 - m);
            float sm = e0 + e1;
            #pragma unroll
            for (int o = 16; o; o >>= 1) sm += __shfl_xor_sync(0xffffffffu, sm, o);
            float inv = 1.f / sm;
            *(float2*)(Ynew + (size_t)row * NCLS + lane * 2) = make_float2(e0 * inv, e1 * inv);
            eAcc += -(m + __logf(sm)); // E_row = -logsumexp(z); fp32 like reference
        }
        if (lane == 0) sWE[wip] = eAcc;
        __syncthreads();
        if (tid == 0) {
            float p = ((((((sWE[0] + sWE[1]) + sWE[2]) + sWE[3]) + sWE[4]) + sWE[5]) + sWE[6]) + sWE[7];
            g_EpartF[it & 1][b] = p;
        }
        grid_sync_((unsigned)(it + 1));
        if (wip == 0) {
            const float4* ep4 = (const float4*)&g_EpartF[it & 1][lane * 8];
            float4 a = __ldcg(ep4);
            float4 c = __ldcg(ep4 + 1);
            float v = ((((((a.x + a.y) + a.z) + a.w) + c.x) + c.y) + c.z) + c.w;
            #pragma unroll
            for (int o = 16; o; o >>= 1) v += __shfl_xor_sync(0xffffffffu, v, o);
            if (lane == 0) {
                sEsh = v;
                sCv = (it >= 2 && fabsf(v - Eprev) <= 1e-8f * fabsf(Eprev)) ? 1 : 0;
            }
        }
        __syncthreads();
        float E = sEsh; int cv = sCv;
        Eprev = E;
        if (cv) { finalIt = it; break; }
    }

    const float* src = (finalIt & 1) ? g_Ya : g_Yb;
    for (int i = tid; i < RPB * NCLS / 4; i += 256) {
        float4 v = __ldcg(((const float4*)(src + (size_t)row0 * NCLS)) + i);
        ((float4*)(out + (size_t)row0 * NCLS))[i] = v;
    }
}

// ---------------- host entry ----------------
extern "C" void kernel_launch(void* const* d_in, const int* in_sizes, int n_in,
                              void* d_out, int out_size) {
    const float* scores = (const float*)d_in[0];
    const float* feats  = (const float*)d_in[1];
    if (n_in >= 2 && in_sizes[0] == NROWS * FDIM) {
        scores = (const float*)d_in[1];
        feats  = (const float*)d_in[0];
    }
    (void)out_size;

    normalize_kernel<<<NROWS, FDIM>>>(feats);
    unary_y0_kernel<<<NROWS / 8, 256>>>(scores);
    gemm_mma_kernel<<<NBLK * (NBLK + 1) / 2, 256>>>();
    knn_kernel<<<NROWS, 256>>>();
    loop_kernel<<<LOOPBLK, 256>>>((float*)d_out);
}

// round 17
// speedup vs baseline: 1.0888x; 1.0888x over previous
#include <cuda_runtime.h>
#include <cuda_bf16.h>
#include <math.h>
#include <float.h>
#include <stdint.h>

#define NROWS 8192
#define FDIM 256
#define NCLS 64
#define KNNK 5
#define MAXSTEPS 100
#define LOOPBLK 256
#define CANDMAX 256

// ---------------- device scratch ----------------
__device__ float          g_fn[NROWS * FDIM];
__device__ __nv_bfloat16  g_fnb[NROWS * FDIM];
__device__ float          g_sq[NROWS];
__device__ __nv_bfloat16  g_dotsb[(size_t)NROWS * NROWS];   // bf16 DISTANCES
__device__ int            g_tmin[NROWS * 64];               // per-(row,128-col-chunk) bf16 min
__device__ float          g_unary[NROWS * NCLS];
__device__ float          g_Ya[NROWS * NCLS];
__device__ float          g_Yb[NROWS * NCLS];
__device__ int            g_idx[NROWS * KNNK];
__device__ float          g_EpartF[2][LOOPBLK];
__device__ unsigned       g_barA;
__device__ volatile unsigned g_barE;

// ---------------- helpers ----------------
__device__ __forceinline__ uint32_t smem_u32(const void* p) {
    uint32_t a;
    asm("{ .reg .u64 t; cvta.to.shared.u64 t, %1; cvt.u32.u64 %0, t; }" : "=r"(a) : "l"(p));
    return a;
}
__device__ __forceinline__ uint32_t packbf(float lo, float hi) {
    uint32_t r;
    asm("cvt.rn.bf16x2.f32 %0, %1, %2;" : "=r"(r) : "f"(hi), "f"(lo)); // d.lo = %2
    return r;
}
__device__ __forceinline__ void cp_async16(uint32_t saddr, const void* gaddr) {
    asm volatile("cp.async.cg.shared.global [%0], [%1], 16;" :: "r"(saddr), "l"(gaddr));
}
__device__ __forceinline__ void cp_commit() { asm volatile("cp.async.commit_group;"); }
__device__ __forceinline__ void cp_wait0() { asm volatile("cp.async.wait_group 0;"); }

// ---------------- normalize feats (fp32 + bf16), compute sq ----------------
__global__ void normalize_kernel(const float* __restrict__ feats) {
    int row = blockIdx.x;
    int t = threadIdx.x;
    __shared__ float red[8];
    float x = feats[row * FDIM + t];
    float v = x * x;
    #pragma unroll
    for (int o = 16; o; o >>= 1) v += __shfl_xor_sync(0xffffffffu, v, o);
    if ((t & 31) == 0) red[t >> 5] = v;
    __syncthreads();
    float tot = red[0] + red[1] + red[2] + red[3] + red[4] + red[5] + red[6] + red[7];
    float y = x / fmaxf(sqrtf(tot), 1e-12f);
    g_fn[row * FDIM + t] = y;
    g_fnb[row * FDIM + t] = __float2bfloat16(y);
    float v2 = y * y;
    #pragma unroll
    for (int o = 16; o; o >>= 1) v2 += __shfl_xor_sync(0xffffffffu, v2, o);
    __syncthreads();
    if ((t & 31) == 0) red[t >> 5] = v2;
    __syncthreads();
    if (t == 0)
        g_sq[row] = red[0] + red[1] + red[2] + red[3] + red[4] + red[5] + red[6] + red[7];
}

// ---------------- unary + Y0 (also resets loop barrier state) ----------------
__global__ void unary_y0_kernel(const float* __restrict__ scores) {
    if (blockIdx.x == 0 && threadIdx.x == 0) { g_barA = 0; g_barE = 0; }
    int w = blockIdx.x * (blockDim.x >> 5) + (threadIdx.x >> 5);
    int lane = threadIdx.x & 31;
    if (w >= NROWS) return;
    float2 s = *(const float2*)(scores + w * NCLS + lane * 2);
    float u0 = -logf(s.x + 1e-10f);
    float u1 = -logf(s.y + 1e-10f);
    *(float2*)(g_unary + w * NCLS + lane * 2) = make_float2(u0, u1);
    float z0 = -u0, z1 = -u1;
    float m = fmaxf(z0, z1);
    #pragma unroll
    for (int o = 16; o; o >>= 1) m = fmaxf(m, __shfl_xor_sync(0xffffffffu, m, o));
    float e0 = expf(z0 - m), e1 = expf(z1 - m);
    float sm = e0 + e1;
    #pragma unroll
    for (int o = 16; o; o >>= 1) sm += __shfl_xor_sync(0xffffffffu, sm, o);
    float inv = 1.f / sm;
    *(float2*)(g_Ya + w * NCLS + lane * 2) = make_float2(e0 * inv, e1 * inv);
}

// ---------------- bf16 mma.sync symmetric GEMM -> bf16 distances + chunk minima ----------------
#define BM 128
#define BN 128
#define BKC 64
#define AST 72     // padded smem row stride (bf16): 144 B = 9 x 16B chunks (odd shift)
#define TST 136    // transpose-staging stride (bf16): 272 B
#define NBLK (NROWS / BM) // 64

__global__ void __launch_bounds__(256) gemm_mma_kernel() {
    __shared__ __align__(16) unsigned char pool[73728];
    __nv_bfloat16 (*As)[BM][AST] = (__nv_bfloat16 (*)[BM][AST])pool;
    __nv_bfloat16 (*Bs)[BN][AST] = (__nv_bfloat16 (*)[BN][AST])(pool + 36864);
    __nv_bfloat16 (*Ts)[TST] = (__nv_bfloat16 (*)[TST])pool;  // reused for mirror
    int* sRowMin = (int*)pool;                // reused for chunk minima
    int* sColMin = (int*)(pool + 512);

    // triangular block decode
    int tt = blockIdx.x, bi = 0;
    while (tt >= NBLK - bi) { tt -= NBLK - bi; bi++; }
    int bj = bi + tt;
    int iBase = bi * BM, jBase = bj * BN;

    int tid = threadIdx.x, lane = tid & 31, wid = tid >> 5;
    int wm = wid & 1, wn = wid >> 1;   // warp tile 64x32 at (wm*64, wn*32)

    // loaders: 64 cols = 8 x 16B chunks per row; 32 rows per pass, 4 passes
    int lrow = tid >> 3;               // 0..31
    int lch = (tid & 7) * 8;           // bf16 offset of 16B chunk
    const __nv_bfloat16* gA = g_fnb + (size_t)(iBase + lrow) * FDIM + lch;
    const __nv_bfloat16* gB = g_fnb + (size_t)(jBase + lrow) * FDIM + lch;

    float acc[4][4][4];
    #pragma unroll
    for (int mi = 0; mi < 4; ++mi)
        #pragma unroll
        for (int ni = 0; ni < 4; ++ni)
            #pragma unroll
            for (int q = 0; q < 4; ++q) acc[mi][ni][q] = 0.f;

    int aRow = wm * 64 + (lane & 15);
    int aCol = ((lane >> 4) << 3);
    int bRow = wn * 32 + (lane & 7);
    int bCol = ((lane >> 3) & 1) << 3;

    // prefetch stage 0
    #pragma unroll
    for (int p = 0; p < 4; ++p) {
        cp_async16(smem_u32(&As[0][lrow + p * 32][lch]), gA + p * 32 * FDIM);
        cp_async16(smem_u32(&Bs[0][lrow + p * 32][lch]), gB + p * 32 * FDIM);
    }
    cp_commit();

    #pragma unroll 1
    for (int kk = 0; kk < FDIM / BKC; ++kk) {
        int buf = kk & 1;
        cp_wait0();
        __syncthreads();
        if (kk < FDIM / BKC - 1) {
            int nb = buf ^ 1, k0 = (kk + 1) * BKC;
            #pragma unroll
            for (int p = 0; p < 4; ++p) {
                cp_async16(smem_u32(&As[nb][lrow + p * 32][lch]), gA + p * 32 * FDIM + k0);
                cp_async16(smem_u32(&Bs[nb][lrow + p * 32][lch]), gB + p * 32 * FDIM + k0);
            }
            cp_commit();
        }
        #pragma unroll
        for (int ks = 0; ks < 4; ++ks) {
            int k0 = ks * 16;
            uint32_t a[4][4], b[4][2];
            #pragma unroll
            for (int mi = 0; mi < 4; ++mi) {
                uint32_t ad = smem_u32(&As[buf][aRow + mi * 16][k0 + aCol]);
                asm volatile(
                    "ldmatrix.sync.aligned.m8n8.x4.shared.b16 {%0,%1,%2,%3}, [%4];"
                    : "=r"(a[mi][0]), "=r"(a[mi][1]), "=r"(a[mi][2]), "=r"(a[mi][3])
                    : "r"(ad));
            }
            #pragma unroll
            for (int ni = 0; ni < 4; ++ni) {
                uint32_t bd = smem_u32(&Bs[buf][bRow + ni * 8][k0 + bCol]);
                asm volatile(
                    "ldmatrix.sync.aligned.m8n8.x2.shared.b16 {%0,%1}, [%2];"
                    : "=r"(b[ni][0]), "=r"(b[ni][1])
                    : "r"(bd));
            }
            #pragma unroll
            for (int mi = 0; mi < 4; ++mi)
                #pragma unroll
                for (int ni = 0; ni < 4; ++ni)
                    asm volatile(
                        "mma.sync.aligned.m16n8k16.row.col.f32.bf16.bf16.f32 "
                        "{%0,%1,%2,%3}, {%4,%5,%6,%7}, {%8,%9}, {%0,%1,%2,%3};"
                        : "+f"(acc[mi][ni][0]), "+f"(acc[mi][ni][1]),
                          "+f"(acc[mi][ni][2]), "+f"(acc[mi][ni][3])
                        : "r"(a[mi][0]), "r"(a[mi][1]), "r"(a[mi][2]), "r"(a[mi][3]),
                          "r"(b[ni][0]), "r"(b[ni][1]));
        }
    }

    // distances (fp32) then bf16 pairs
    int r0 = wm * 64 + (lane >> 2);
    int c0 = wn * 32 + (lane & 3) * 2;
    float sqr[8], sqc[8];
    #pragma unroll
    for (int mi = 0; mi < 4; ++mi) {
        sqr[2 * mi]     = __ldg(&g_sq[iBase + r0 + mi * 16]);
        sqr[2 * mi + 1] = __ldg(&g_sq[iBase + r0 + mi * 16 + 8]);
    }
    #pragma unroll
    for (int ni = 0; ni < 4; ++ni) {
        sqc[2 * ni]     = __ldg(&g_sq[jBase + c0 + ni * 8]);
        sqc[2 * ni + 1] = __ldg(&g_sq[jBase + c0 + ni * 8 + 1]);
    }
    uint32_t pk01[4][4], pk23[4][4];
    #pragma unroll
    for (int mi = 0; mi < 4; ++mi)
        #pragma unroll
        for (int ni = 0; ni < 4; ++ni) {
            float d0 = fmaxf(fmaf(-2.f, acc[mi][ni][0], sqr[2 * mi] + sqc[2 * ni]), 0.f);
            float d1 = fmaxf(fmaf(-2.f, acc[mi][ni][1], sqr[2 * mi] + sqc[2 * ni + 1]), 0.f);
            float d2 = fmaxf(fmaf(-2.f, acc[mi][ni][2], sqr[2 * mi + 1] + sqc[2 * ni]), 0.f);
            float d3 = fmaxf(fmaf(-2.f, acc[mi][ni][3], sqr[2 * mi + 1] + sqc[2 * ni + 1]), 0.f);
            pk01[mi][ni] = packbf(d0, d1);
            pk23[mi][ni] = packbf(d2, d3);
        }

    // main tile write
    #pragma unroll
    for (int mi = 0; mi < 4; ++mi)
        #pragma unroll
        for (int ni = 0; ni < 4; ++ni) {
            size_t row = (size_t)(iBase + r0 + mi * 16);
            int col = jBase + c0 + ni * 8;
            *(uint32_t*)(g_dotsb + row * NROWS + col) = pk01[mi][ni];
            *(uint32_t*)(g_dotsb + (row + 8) * NROWS + col) = pk23[mi][ni];
        }

    // ---- per-row / per-col chunk minima (bf16 uint16 domain) ----
    __syncthreads();          // everyone done with As/Bs before pool reuse
    if (tid < 128) { sRowMin[tid] = 0x7FFFFFFF; sColMin[tid] = 0x7FFFFFFF; }
    __syncthreads();
    #pragma unroll
    for (int mi = 0; mi < 4; ++mi) {
        uint32_t m01 = 0xFFFFu, m23 = 0xFFFFu;
        #pragma unroll
        for (int ni = 0; ni < 4; ++ni) {
            m01 = min(m01, min(pk01[mi][ni] & 0xFFFFu, pk01[mi][ni] >> 16));
            m23 = min(m23, min(pk23[mi][ni] & 0xFFFFu, pk23[mi][ni] >> 16));
        }
        atomicMin(&sRowMin[r0 + mi * 16], (int)m01);
        atomicMin(&sRowMin[r0 + mi * 16 + 8], (int)m23);
    }
    #pragma unroll
    for (int ni = 0; ni < 4; ++ni) {
        uint32_t lo = 0xFFFFu, hi = 0xFFFFu;
        #pragma unroll
        for (int mi = 0; mi < 4; ++mi) {
            lo = min(lo, min(pk01[mi][ni] & 0xFFFFu, pk23[mi][ni] & 0xFFFFu));
            hi = min(hi, min(pk01[mi][ni] >> 16, pk23[mi][ni] >> 16));
        }
        atomicMin(&sColMin[c0 + ni * 8], (int)lo);
        atomicMin(&sColMin[c0 + ni * 8 + 1], (int)hi);
    }
    __syncthreads();
    if (tid < 128) {
        g_tmin[(size_t)(iBase + tid) * NBLK + bj] = sRowMin[tid];
        if (bi != bj)
            g_tmin[(size_t)(jBase + tid) * NBLK + bi] = sColMin[tid];
    }

    // mirror (distance matrix symmetric): smem-staged transpose
    if (bi != bj) {
        __syncthreads();   // g_tmin smem reads done before Ts overwrites pool
        #pragma unroll
        for (int mi = 0; mi < 4; ++mi)
            #pragma unroll
            for (int ni = 0; ni < 4; ++ni) {
                int rr = r0 + mi * 16;
                int cc = c0 + ni * 8;
                *(unsigned short*)&Ts[cc][rr]         = (unsigned short)(pk01[mi][ni] & 0xFFFFu);
                *(unsigned short*)&Ts[cc + 1][rr]     = (unsigned short)(pk01[mi][ni] >> 16);
                *(unsigned short*)&Ts[cc][rr + 8]     = (unsigned short)(pk23[mi][ni] & 0xFFFFu);
                *(unsigned short*)&Ts[cc + 1][rr + 8] = (unsigned short)(pk23[mi][ni] >> 16);
            }
        __syncthreads();
        #pragma unroll
        for (int q = 0; q < 8; ++q) {
            int idx = q * 256 + tid;       // 2048 uint4 chunks: 16 per 128-col row
            int c = idx >> 4;              // 0..127
            int ch = (idx & 15) * 8;       // 0..120
            uint4 v = *(const uint4*)&Ts[c][ch];
            *(uint4*)(g_dotsb + (size_t)(jBase + c) * NROWS + iBase + ch) = v;
        }
    }
}

// ---------------- knn: chunk-min pruned select + exact refine ----------------
__device__ __forceinline__ bool cless(float v1, int i1, float v2, int i2) {
    return (v1 < v2) || (v1 == v2 && i1 < i2);
}

__global__ void __launch_bounds__(128) knn_kernel() {
    __shared__ int sMins[NBLK];
    __shared__ int sChk[NBLK];
    __shared__ int sNchk;
    __shared__ uint32_t sTau;
    __shared__ int sCnt;
    __shared__ int sCand[CANDMAX];
    __shared__ float sDv[CANDMAX];
    __shared__ int sDj[CANDMAX];

    int row = blockIdx.x;
    int t = threadIdx.x, lane = t & 31, wid = t >> 5;

    if (t < NBLK) sMins[t] = g_tmin[(size_t)row * NBLK + t];
    if (t == 0) { sCnt = 0; sNchk = 0; }
    __syncthreads();

    // tau = 16th smallest of 64 chunk minima (>=16 elements <= tau in the row)
    if (t < 32) {
        uint32_t v0 = ((uint32_t)sMins[t] << 16) | (uint32_t)t;
        uint32_t v1 = ((uint32_t)sMins[t + 32] << 16) | (uint32_t)(t + 32);
        uint32_t tau = 0;
        #pragma unroll
        for (int r = 0; r < 16; ++r) {
            uint32_t g = min(v0, v1);
            #pragma unroll
            for (int o = 16; o; o >>= 1) g = min(g, __shfl_xor_sync(0xffffffffu, g, o));
            tau = g >> 16;
            if (v0 == g) v0 = 0xFFFFFFFFu;
            if (v1 == g) v1 = 0xFFFFFFFFu;
        }
        if (t == 0) sTau = tau;
    }
    __syncthreads();
    uint32_t tau = sTau;

    // chunks that can contain candidates
    if (t < NBLK && (uint32_t)sMins[t] <= tau) {
        int p = atomicAdd(&sNchk, 1);
        sChk[p] = t;
    }
    __syncthreads();
    int nChk = sNchk;

    // scan only those chunks (warp per chunk, stride 4)
    const __nv_bfloat16* __restrict__ dr = g_dotsb + (size_t)row * NROWS;
    for (int c = wid; c < nChk; c += 4) {
        int base = sChk[c] * 128;
        uint2 v = *(const uint2*)(dr + base + lane * 4);
        int j0 = base + lane * 4;
        if ((v.x & 0xFFFFu) <= tau) { int p = atomicAdd(&sCnt, 1); if (p < CANDMAX) sCand[p] = j0; }
        if ((v.x >> 16) <= tau)     { int p = atomicAdd(&sCnt, 1); if (p < CANDMAX) sCand[p] = j0 + 1; }
        if ((v.y & 0xFFFFu) <= tau) { int p = atomicAdd(&sCnt, 1); if (p < CANDMAX) sCand[p] = j0 + 2; }
        if ((v.y >> 16) <= tau)     { int p = atomicAdd(&sCnt, 1); if (p < CANDMAX) sCand[p] = j0 + 3; }
    }
    __syncthreads();
    int C = min(sCnt, CANDMAX);

    // exact fp32 refine (warp per candidate, stride 4); g_fn is L2-resident
    float sqi = g_sq[row];
    const float* fr = g_fn + (size_t)row * FDIM;
    float4 m0 = *(const float4*)(fr + lane * 8);
    float4 m1 = *(const float4*)(fr + lane * 8 + 4);
    for (int c = wid; c < C; c += 4) {
        int j = sCand[c];
        const float* fj = g_fn + (size_t)j * FDIM;
        float4 a0 = *(const float4*)(fj + lane * 8);
        float4 a1 = *(const float4*)(fj + lane * 8 + 4);
        float acc = m0.x * a0.x + m0.y * a0.y + m0.z * a0.z + m0.w * a0.w
                  + m1.x * a1.x + m1.y * a1.y + m1.z * a1.z + m1.w * a1.w;
        #pragma unroll
        for (int o = 16; o; o >>= 1) acc += __shfl_xor_sync(0xffffffffu, acc, o);
        if (lane == 0) {
            sDv[c] = fmaxf(sqi + g_sq[j] - 2.f * acc, 0.f);
            sDj[c] = j;
        }
    }
    __syncthreads();

    // exact top-5 (value then index tie-break), excluding self
    if (t == 0) {
        for (int r = 0; r < KNNK; ++r) {
            float best = FLT_MAX; int bi2 = 0x7fffffff, bc = -1;
            for (int c = 0; c < C; ++c)
                if (sDj[c] != row && cless(sDv[c], sDj[c], best, bi2)) {
                    best = sDv[c]; bi2 = sDj[c]; bc = c;
                }
            g_idx[row * KNNK + r] = bi2;
            sDv[bc] = FLT_MAX; sDj[bc] = 0x7fffffff;
        }
    }
}

// ---------------- persistent fused mean-field loop (measured-good R9 shape) ----------------
__device__ __forceinline__ void grid_sync_(unsigned epoch) {
    __syncthreads();
    if (threadIdx.x == 0) {
        __threadfence();
        unsigned prev = atomicAdd(&g_barA, 1u);
        if (prev == epoch * LOOPBLK - 1) {
            __threadfence();
            g_barE = epoch;
        } else {
            while (g_barE < epoch) { __nanosleep(32); }
            __threadfence();
        }
    }
    __syncthreads();
}

#define RPB (NROWS / LOOPBLK)   // 32 rows per block

__global__ void __launch_bounds__(256) loop_kernel(float* __restrict__ out) {
    __shared__ float sU[RPB * NCLS];
    __shared__ int sNb[RPB * KNNK];
    __shared__ float sWE[8];
    __shared__ float sEsh;
    __shared__ int sCv;
    int b = blockIdx.x, tid = threadIdx.x, wip = tid >> 5, lane = tid & 31;
    int row0 = b * RPB;

    for (int i = tid; i < RPB * NCLS / 4; i += 256)
        ((float4*)sU)[i] = ((const float4*)(g_unary + (size_t)row0 * NCLS))[i];
    for (int i = tid; i < RPB * KNNK; i += 256)
        sNb[i] = g_idx[row0 * KNNK + i];
    __syncthreads();

    float Eprev = __int_as_float(0x7F800000); // +inf
    int finalIt = MAXSTEPS - 1;

    for (int it = 0; it < MAXSTEPS; ++it) {
        const float* Yold = (it & 1) ? g_Yb : g_Ya;
        float* Ynew = (it & 1) ? g_Ya : g_Yb;
        float eAcc = 0.f;
        #pragma unroll
        for (int q = 0; q < RPB / 8; ++q) {
            int rl = wip * (RPB / 8) + q, row = row0 + rl;
            const int* nb = &sNb[rl * KNNK];
            float2 u = *(const float2*)&sU[rl * NCLS + lane * 2];
            float2 p0 = __ldcg((const float2*)(Yold + (size_t)nb[0] * NCLS + lane * 2));
            float2 p1 = __ldcg((const float2*)(Yold + (size_t)nb[1] * NCLS + lane * 2));
            float2 p2 = __ldcg((const float2*)(Yold + (size_t)nb[2] * NCLS + lane * 2));
            float2 p3 = __ldcg((const float2*)(Yold + (size_t)nb[3] * NCLS + lane * 2));
            float2 p4 = __ldcg((const float2*)(Yold + (size_t)nb[4] * NCLS + lane * 2));
            float z0 = -u.x + p0.x + p1.x + p2.x + p3.x + p4.x;
            float z1 = -u.y + p0.y + p1.y + p2.y + p3.y + p4.y;
            float m = fmaxf(z0, z1);
            #pragma unroll
            for (int o = 16; o; o >>= 1) m = fmaxf(m, __shfl_xor_sync(0xffffffffu, m, o));
            float e0 = __expf(z0 - m), e1 = __expf(z1 - m);
            float sm = e0 + e1;
            #pragma unroll
            for (int o = 16; o; o >>= 1) sm += __shfl_xor_sync(0xffffffffu, sm, o);
            float inv = 1.f / sm;
            *(float2*)(Ynew + (size_t)row * NCLS + lane * 2) = make_float2(e0 * inv, e1 * inv);
            eAcc += -(m + __logf(sm)); // E_row = -logsumexp(z); fp32 like reference
        }
        if (lane == 0) sWE[wip] = eAcc;
        __syncthreads();
        if (tid == 0) {
            float p = ((((((sWE[0] + sWE[1]) + sWE[2]) + sWE[3]) + sWE[4]) + sWE[5]) + sWE[6]) + sWE[7];
            g_EpartF[it & 1][b] = p;
        }
        grid_sync_((unsigned)(it + 1));
        if (wip == 0) {
            const float4* ep4 = (const float4*)&g_EpartF[it & 1][lane * 8];
            float4 a = __ldcg(ep4);
            float4 c = __ldcg(ep4 + 1);
            float v = ((((((a.x + a.y) + a.z) + a.w) + c.x) + c.y) + c.z) + c.w;
            #pragma unroll
            for (int o = 16; o; o >>= 1) v += __shfl_xor_sync(0xffffffffu, v, o);
            if (lane == 0) {
                sEsh = v;
                sCv = (it >= 2 && fabsf(v - Eprev) <= 1e-8f * fabsf(Eprev)) ? 1 : 0;
            }
        }
        __syncthreads();
        float E = sEsh; int cv = sCv;
        Eprev = E;
        if (cv) { finalIt = it; break; }
    }

    const float* src = (finalIt & 1) ? g_Ya : g_Yb;
    for (int i = tid; i < RPB * NCLS / 4; i += 256) {
        float4 v = __ldcg(((const float4*)(src + (size_t)row0 * NCLS)) + i);
        ((float4*)(out + (size_t)row0 * NCLS))[i] = v;
    }
}

// ---------------- host entry ----------------
extern "C" void kernel_launch(void* const* d_in, const int* in_sizes, int n_in,
                              void* d_out, int out_size) {
    const float* scores = (const float*)d_in[0];
    const float* feats  = (const float*)d_in[1];
    if (n_in >= 2 && in_sizes[0] == NROWS * FDIM) {
        scores = (const float*)d_in[1];
        feats  = (const float*)d_in[0];
    }
    (void)out_size;

    normalize_kernel<<<NROWS, FDIM>>>(feats);
    unary_y0_kernel<<<NROWS / 8, 256>>>(scores);
    gemm_mma_kernel<<<NBLK * (NBLK + 1) / 2, 256>>>();
    knn_kernel<<<NROWS, 128>>>();
    loop_kernel<<<LOOPBLK, 256>>>((float*)d_out);
}